// round 12
// baseline (speedup 1.0000x reference)
#include <cuda_runtime.h>
#include <math_constants.h>

// Density-aware Chamfer loss, B=4, N=8192, 3D fp32.
// R12: R11's sort + pruned sweep, with (1) QPT=4/TPB=128 so each warp
// amortizes its scan window over 128 sorted-adjacent queries, (2) finalize
// fused into one deterministic kernel (3 launches total).
//  sort_kernel : per cloud (8 x 512 thr) stable parallel counting sort by
//                x-bin (deterministic); zeroes g_cnt.
//  nn_kernel   : sorted ref cloud in smem + monotone group x-bounds; uniform
//                home range from warp's first/last query; outward sweep with
//                warp-vote early exit (inclusive + margin). Packed
//                fma.rn.f32x2 bodies; winning-group bit-exact rescan ->
//                min ORIGINAL index among ties; inline histogram atomics.
//  finalize_kernel : grid 4 x 1024, deterministic tree reduce -> out[b].

#define B_CONST   4
#define N_CONST   8192
#define NCLOUD    8
#define NBINS     256
#define NCHUNKS   (N_CONST / 32)       // 256

#define TPB       128
#define QPT       4
#define QPW       (32 * QPT)           // 128 queries per warp
#define QPC       (TPB * QPT)          // 512 queries / CTA
#define QCHUNKS   (N_CONST / QPC)      // 16
#define GROUP     32
#define JPG       (GROUP / 2)          // 16
#define NGROUPS   (N_CONST / GROUP)    // 256

#define SORT_SMEM (131072 + 65536 + 8192 + 1024 + 1024)   // 206848
#define NN_SMEM   ((32768 + 8192 + 256 + 256) * 4)        // 165888

__device__ float4 g_sorted[NCLOUD * N_CONST];
__device__ int    g_sidx  [NCLOUD * N_CONST];
__device__ int    g_idx   [2 * B_CONST * N_CONST];
__device__ int    g_cnt   [2 * B_CONST * N_CONST];

__device__ __forceinline__ int bin_of(float x) {
    int bi = (int)floorf((x + 5.2f) * (256.0f / 10.4f));
    return min(max(bi, 0), NBINS - 1);
}

// cloud 0..3 = gts[b], cloud 4..7 = preds[b]
__global__ __launch_bounds__(512, 1) void sort_kernel(const float* __restrict__ gts,
                                                      const float* __restrict__ preds) {
    extern __shared__ char sm_raw[];
    float4*        s_pts  = (float4*)sm_raw;                          // [8192]
    unsigned char* s_cnt  = (unsigned char*)(sm_raw + 131072);        // [chunk][bin]
    unsigned char* s_rank = (unsigned char*)(sm_raw + 131072 + 65536);// [8192]
    int*           s_hist = (int*)(sm_raw + 131072 + 65536 + 8192);   // [256]
    int*           s_base = s_hist + NBINS;                           // [256]

    const int tid  = threadIdx.x;
    const int cloud = blockIdx.x;
    const float* src = (cloud < 4) ? gts + (long)cloud * N_CONST * 3
                                   : preds + (long)(cloud - 4) * N_CONST * 3;

    for (int i = tid; i < N_CONST; i += 512) g_cnt[cloud * N_CONST + i] = 0;
    for (int i = tid; i < (NCHUNKS * NBINS) / 4; i += 512) ((int*)s_cnt)[i] = 0;
    for (int i = tid; i < N_CONST; i += 512) {
        float x = src[3 * i], y = src[3 * i + 1], z = src[3 * i + 2];
        s_pts[i] = make_float4(x, y, z, x * x + y * y + z * z);
    }
    __syncthreads();

    {
        const int w = tid >> 5, lane = tid & 31;
        for (int cc = 0; cc < NCHUNKS / 16; cc++) {
            int c = w * (NCHUNKS / 16) + cc;
            int i = c * 32 + lane;
            int bi = bin_of(s_pts[i].x);
            unsigned mask = __match_any_sync(0xffffffffu, bi);
            s_rank[i] = (unsigned char)__popc(mask & ((1u << lane) - 1u));
            if ((int)(__ffs(mask) - 1) == lane)
                s_cnt[c * NBINS + bi] = (unsigned char)__popc(mask);
        }
    }
    __syncthreads();

    if (tid < NBINS) {
        int run = 0;
        for (int c = 0; c < NCHUNKS; c++) {
            int v = s_cnt[c * NBINS + tid];
            s_cnt[c * NBINS + tid] = (unsigned char)run;
            run += v;
        }
        s_hist[tid] = run;
    }
    __syncthreads();
    if (tid == 0) {
        int run = 0;
        for (int bb = 0; bb < NBINS; bb++) { s_base[bb] = run; run += s_hist[bb]; }
    }
    __syncthreads();

    for (int i = tid; i < N_CONST; i += 512) {
        float4 p = s_pts[i];
        int bi = bin_of(p.x);
        int pos = s_base[bi] + (int)s_cnt[(i >> 5) * NBINS + bi] + (int)s_rank[i];
        g_sorted[cloud * N_CONST + pos] = p;
        g_sidx[cloud * N_CONST + pos] = i;
    }
}

// Packed body over QPT=4 queries (bit-exact with rescan).
#define NN_BODY(G)                                                              \
    {                                                                           \
        const float* gb = s_tile + (G) * (JPG * 8);                             \
        float mE[QPT], mO[QPT];                                                 \
        _Pragma("unroll")                                                       \
        for (int k = 0; k < QPT; k++) { mE[k] = CUDART_INF_F; mO[k] = CUDART_INF_F; } \
        _Pragma("unroll")                                                       \
        for (int jj = 0; jj < JPG; jj++) {                                      \
            ulonglong2 A  = *(const ulonglong2*)(gb + jj * 8);                  \
            ulonglong2 Bv = *(const ulonglong2*)(gb + jj * 8 + 4);              \
            _Pragma("unroll")                                                   \
            for (int k = 0; k < QPT; k++) {                                     \
                float tlo, thi;                                                 \
                asm("{\n\t.reg .b64 t;\n\t"                                     \
                    "fma.rn.f32x2 t, %2, %3, %4;\n\t"                           \
                    "fma.rn.f32x2 t, %5, %6, t;\n\t"                            \
                    "fma.rn.f32x2 t, %7, %8, t;\n\t"                            \
                    "mov.b64 {%0, %1}, t;\n\t}"                                 \
                    : "=f"(tlo), "=f"(thi)                                      \
                    : "l"(qx2[k]), "l"(A.x), "l"(Bv.y),                         \
                      "l"(qy2[k]), "l"(A.y), "l"(qz2[k]), "l"(Bv.x));           \
                mE[k] = fminf(mE[k], tlo); mO[k] = fminf(mO[k], thi);           \
            }                                                                   \
        }                                                                       \
        _Pragma("unroll")                                                       \
        for (int k = 0; k < QPT; k++) {                                         \
            float m = fminf(mE[k], mO[k]);                                      \
            if (m < best[k]) { best[k] = m; gidw[k] = (G); bestd[k] = m + cc[k]; } \
        }                                                                       \
    }

// db = dir*B + b.  dir 0: queries = gts, refs = preds. dir 1: swapped.
__global__ __launch_bounds__(TPB, 1) void nn_kernel() {
    extern __shared__ float sm[];
    float* s_tile = sm;                         // 32768 floats, jj-interleaved
    int*   s_sidx = (int*)(sm + 32768);         // 8192 orig indices
    float* s_glo  = sm + 32768 + 8192;          // 256, monotone non-decreasing
    float* s_ghi  = s_glo + NGROUPS;            // 256, monotone non-decreasing

    const int tid  = threadIdx.x;
    const int lane = tid & 31;
    const int wid  = tid >> 5;
    const int db   = blockIdx.y;
    const int b    = db & 3;
    const int dir  = db >> 2;
    const int qc   = (dir == 0) ? b : 4 + b;
    const int rc   = (dir == 0) ? 4 + b : b;
    const float4* gr  = g_sorted + rc * N_CONST;
    const int*    gri = g_sidx   + rc * N_CONST;
    const float4* gq  = g_sorted + qc * N_CONST;
    const int*    gqi = g_sidx   + qc * N_CONST;

    for (int j = tid; j < N_CONST; j += TPB) {
        float4 p = gr[j];
        int jj = j >> 1, h = j & 1;
        float* pp = s_tile + jj * 8;
        pp[0 + h] = p.x; pp[2 + h] = p.y; pp[4 + h] = p.z; pp[6 + h] = p.w;
        s_sidx[j] = gri[j];
    }
    __syncthreads();
    if (tid < NGROUPS) {   // TPB=128: two rounds
        int g0 = tid, g1 = tid + TPB;
        int a0 = g0 * GROUP, a1 = g0 * GROUP + GROUP - 1;
        s_glo[g0] = s_tile[(a0 >> 1) * 8 + (a0 & 1)];
        s_ghi[g0] = s_tile[(a1 >> 1) * 8 + (a1 & 1)];
        a0 = g1 * GROUP; a1 = g1 * GROUP + GROUP - 1;
        s_glo[g1] = s_tile[(a0 >> 1) * 8 + (a0 & 1)];
        s_ghi[g1] = s_tile[(a1 >> 1) * 8 + (a1 & 1)];
    }
    __syncthreads();

    const int wbase = blockIdx.x * QPC + wid * QPW;

    float qx[QPT], cc[QPT], qxs[QPT], qys[QPT], qzs[QPT];
    unsigned long long qx2[QPT], qy2[QPT], qz2[QPT];
    float best[QPT], bestd[QPT];
    int gidw[QPT], oq[QPT];

    #pragma unroll
    for (int k = 0; k < QPT; k++) {
        int qpos = wbase + lane + k * 32;     // coalesced
        float4 qp = gq[qpos];
        oq[k] = gqi[qpos];
        qx[k] = qp.x; cc[k] = qp.w;
        qxs[k] = -2.0f * qp.x; qys[k] = -2.0f * qp.y; qzs[k] = -2.0f * qp.z;
        asm("mov.b64 %0, {%1, %1};" : "=l"(qx2[k]) : "f"(qxs[k]));
        asm("mov.b64 %0, {%1, %1};" : "=l"(qy2[k]) : "f"(qys[k]));
        asm("mov.b64 %0, {%1, %1};" : "=l"(qz2[k]) : "f"(qzs[k]));
        best[k] = CUDART_INF_F; bestd[k] = CUDART_INF_F; gidw[k] = 0;
    }

    // uniform home range from warp's first/last query x (sorted order)
    const float uqlo = gq[wbase].x;
    const float uqhi = gq[wbase + QPW - 1].x;
    int gmn, gmx;
    {
        int lo = 0, hi = NGROUPS - 1;
        #pragma unroll
        for (int it = 0; it < 8; it++) {
            int mid = (lo + hi + 1) >> 1;
            if (s_glo[mid] <= uqlo) lo = mid; else hi = mid - 1;
        }
        gmn = lo;
        lo = 0; hi = NGROUPS - 1;
        #pragma unroll
        for (int it = 0; it < 8; it++) {
            int mid = (lo + hi + 1) >> 1;
            if (s_glo[mid] <= uqhi) lo = mid; else hi = mid - 1;
        }
        gmx = lo;
    }

    for (int g = gmn; g <= gmx; g++) NN_BODY(g);

    // right sweep: s_glo monotone; first all-lane prune => provably done
    for (int g = gmx + 1; g < NGROUPS; g++) {
        bool need = false;
        #pragma unroll
        for (int k = 0; k < QPT; k++) {
            float e = s_glo[g] - qx[k];
            need |= (e * e <= bestd[k] * 1.000002f + 1e-7f);
        }
        if (!__any_sync(0xffffffffu, need)) break;
        NN_BODY(g);
    }
    // left sweep: s_ghi monotone
    for (int g = gmn - 1; g >= 0; g--) {
        bool need = false;
        #pragma unroll
        for (int k = 0; k < QPT; k++) {
            float e = qx[k] - s_ghi[g];
            need |= (e * e <= bestd[k] * 1.000002f + 1e-7f);
        }
        if (!__any_sync(0xffffffffu, need)) break;
        NN_BODY(g);
    }

    // rescan winning group: bit-exact recompute, min ORIGINAL index among ties
    #pragma unroll
    for (int k = 0; k < QPT; k++) {
        const int base = gidw[k] * GROUP;
        int bi = 0x7fffffff;
        #pragma unroll 8
        for (int j = 0; j < GROUP; j++) {
            int pos = base + j;
            const float* p = s_tile + (pos >> 1) * 8;
            int h = pos & 1;
            float t = fmaf(qxs[k], p[0 + h], p[6 + h]);
            t = fmaf(qys[k], p[2 + h], t);
            t = fmaf(qzs[k], p[4 + h], t);
            if (t == best[k]) bi = min(bi, s_sidx[pos]);
        }
        g_idx[db * N_CONST + oq[k]] = bi;
        atomicAdd(&g_cnt[db * N_CONST + bi], 1);
    }
}

// One CTA per b: both dirs, deterministic tree reduce -> out[b]
__global__ __launch_bounds__(1024) void finalize_kernel(const float* __restrict__ gts,
                                                        const float* __restrict__ preds,
                                                        float* __restrict__ out) {
    __shared__ float ssum[1024];
    const int b = blockIdx.x;
    const int tid = threadIdx.x;
    float acc = 0.0f;

    #pragma unroll
    for (int dir = 0; dir < 2; dir++) {
        const int db = dir * B_CONST + b;
        const float* qptr = (dir == 0) ? gts : preds;
        const float* rptr = (dir == 0) ? preds : gts;
        const float* qb = qptr + (long)b * N_CONST * 3;
        const float* rb = rptr + (long)b * N_CONST * 3;
        #pragma unroll
        for (int i = 0; i < N_CONST / 1024; i++) {
            int q = tid + i * 1024;
            int id = g_idx[db * N_CONST + q];
            float dx = qb[3 * q + 0] - rb[3 * id + 0];
            float dy = qb[3 * q + 1] - rb[3 * id + 1];
            float dz = qb[3 * q + 2] - rb[3 * id + 2];
            float d  = dx * dx + dy * dy + dz * dz;
            float c  = (float)g_cnt[db * N_CONST + id];
            acc += 1.0f - expf(-d) / (c + 1e-6f);   // ALPHA=1, N_LAMBDA=1, frac=1
        }
    }

    ssum[tid] = acc;
    __syncthreads();
    for (int off = 512; off > 0; off >>= 1) {
        if (tid < off) ssum[tid] += ssum[tid + off];
        __syncthreads();
    }
    if (tid == 0) out[b] = ssum[0] / (2.0f * (float)N_CONST);
}

extern "C" void kernel_launch(void* const* d_in, const int* in_sizes, int n_in,
                              void* d_out, int out_size) {
    const float* gts   = (const float*)d_in[0];
    const float* preds = (const float*)d_in[1];
    float* out = (float*)d_out;

    cudaFuncSetAttribute(sort_kernel, cudaFuncAttributeMaxDynamicSharedMemorySize, SORT_SMEM);
    cudaFuncSetAttribute(nn_kernel, cudaFuncAttributeMaxDynamicSharedMemorySize, NN_SMEM);

    sort_kernel<<<NCLOUD, 512, SORT_SMEM>>>(gts, preds);
    nn_kernel<<<dim3(QCHUNKS, 2 * B_CONST), TPB, NN_SMEM>>>();
    finalize_kernel<<<B_CONST, 1024>>>(gts, preds, out);
}

// round 13
// speedup vs baseline: 1.1062x; 1.1062x over previous
#include <cuda_runtime.h>
#include <math_constants.h>

// Density-aware Chamfer loss, B=4, N=8192, 3D fp32.
// R13: fast parallel sort + R11 nn (QPT=2/TPB=256) with EXACT envelope
// pruning + fused finalize. 3 launches.
//  sort_kernel : per cloud (8 x 1024 thr) stable counting sort by x-bin.
//                Quarter-split chunk prefixes (64-iter loops), warp-scan bin
//                base. Deterministic. Zeroes g_cnt.
//  nn_kernel   : sorted ref cloud in smem; TRUE group min/max x + suffix-min
//                / prefix-max envelopes => exact outward-sweep pruning.
//                Packed fma.rn.f32x2 bodies; winning-group bit-exact rescan
//                -> min ORIGINAL index among ties; inline histogram atomics.
//  finalize_kernel : grid 4 x 1024, deterministic tree reduce -> out[b].

#define B_CONST   4
#define N_CONST   8192
#define NCLOUD    8
#define NBINS     256
#define NCHUNKS   (N_CONST / 32)       // 256
#define CPQ       (NCHUNKS / 4)        // 64 chunks per quarter

#define TPB       256
#define QPT       2
#define QPC       (TPB * QPT)          // 512 queries / CTA
#define QCHUNKS   (N_CONST / QPC)      // 16
#define GROUP     32
#define JPG       (GROUP / 2)          // 16
#define NGROUPS   (N_CONST / GROUP)    // 256

// sort smem: pts 131072 + cnt 65536 + rank 8192 + qsum 4096 + hist 1024 + base 1024
#define SORT_SMEM (131072 + 65536 + 8192 + 4096 + 1024 + 1024)   // 210944
// nn smem: tile 32768f + sidx 8192i + gmin/gmax/suf/pmax 4*256f
#define NN_SMEM   ((32768 + 8192 + 4 * 256) * 4)                 // 167936

__device__ float4 g_sorted[NCLOUD * N_CONST];
__device__ int    g_sidx  [NCLOUD * N_CONST];
__device__ int    g_idx   [2 * B_CONST * N_CONST];
__device__ int    g_cnt   [2 * B_CONST * N_CONST];

__device__ __forceinline__ int bin_of(float x) {
    int bi = (int)floorf((x + 5.2f) * (256.0f / 10.4f));
    return min(max(bi, 0), NBINS - 1);
}

// cloud 0..3 = gts[b], cloud 4..7 = preds[b]
__global__ __launch_bounds__(1024, 1) void sort_kernel(const float* __restrict__ gts,
                                                       const float* __restrict__ preds) {
    extern __shared__ char sm_raw[];
    float4*        s_pts  = (float4*)sm_raw;                            // [8192]
    unsigned char* s_cnt  = (unsigned char*)(sm_raw + 131072);          // [chunk][bin]
    unsigned char* s_rank = (unsigned char*)(sm_raw + 131072 + 65536);  // [8192]
    int*           s_qsum = (int*)(sm_raw + 131072 + 65536 + 8192);     // [4][256]
    int*           s_hist = s_qsum + 4 * NBINS;                         // [256]
    int*           s_base = s_hist + NBINS;                             // [256]

    const int tid   = threadIdx.x;
    const int cloud = blockIdx.x;
    const float* src = (cloud < 4) ? gts + (long)cloud * N_CONST * 3
                                   : preds + (long)(cloud - 4) * N_CONST * 3;

    for (int i = tid; i < N_CONST; i += 1024) g_cnt[cloud * N_CONST + i] = 0;
    for (int i = tid; i < (NCHUNKS * NBINS) / 4; i += 1024) ((int*)s_cnt)[i] = 0;
    for (int i = tid; i < N_CONST; i += 1024) {
        float x = src[3 * i], y = src[3 * i + 1], z = src[3 * i + 2];
        s_pts[i] = make_float4(x, y, z, x * x + y * y + z * z);
    }
    __syncthreads();

    // per-chunk stable ranks + per-chunk-bin counts (32 warps x 8 chunks)
    {
        const int w = tid >> 5, lane = tid & 31;
        #pragma unroll
        for (int cc = 0; cc < NCHUNKS / 32; cc++) {
            int c = w * (NCHUNKS / 32) + cc;
            int i = c * 32 + lane;
            int bi = bin_of(s_pts[i].x);
            unsigned mask = __match_any_sync(0xffffffffu, bi);
            s_rank[i] = (unsigned char)__popc(mask & ((1u << lane) - 1u));
            if ((int)(__ffs(mask) - 1) == lane)
                s_cnt[c * NBINS + bi] = (unsigned char)__popc(mask);
        }
    }
    __syncthreads();

    // quarter sums: thread = (quarter, bin)
    {
        const int bi = tid & (NBINS - 1);
        const int qt = tid >> 8;           // 0..3
        int run = 0;
        #pragma unroll 8
        for (int c = qt * CPQ; c < (qt + 1) * CPQ; c++)
            run += s_cnt[c * NBINS + bi];
        s_qsum[qt * NBINS + bi] = run;
    }
    __syncthreads();

    // per-bin: exclusive scan of 4 quarter sums; total -> hist
    if (tid < NBINS) {
        int r0 = 0;
        #pragma unroll
        for (int qt = 0; qt < 4; qt++) {
            int v = s_qsum[qt * NBINS + tid];
            s_qsum[qt * NBINS + tid] = r0;
            r0 += v;
        }
        s_hist[tid] = r0;
    }
    __syncthreads();

    // bin base: warp scan (lane owns 8 bins)
    if (tid < 32) {
        int lsum = 0;
        #pragma unroll
        for (int j = 0; j < 8; j++) lsum += s_hist[tid * 8 + j];
        int excl = lsum;
        #pragma unroll
        for (int o = 1; o < 32; o <<= 1) {
            int v = __shfl_up_sync(0xffffffffu, excl, o);
            if ((tid & 31) >= o) excl += v;
        }
        excl -= lsum;   // exclusive
        int run = excl;
        #pragma unroll
        for (int j = 0; j < 8; j++) {
            s_base[tid * 8 + j] = run;
            run += s_hist[tid * 8 + j];
        }
    }
    __syncthreads();

    // chunk-prefix writeback per (quarter, bin), 64-iter loops
    {
        const int bi = tid & (NBINS - 1);
        const int qt = tid >> 8;
        int run = s_qsum[qt * NBINS + bi];
        #pragma unroll 8
        for (int c = qt * CPQ; c < (qt + 1) * CPQ; c++) {
            int v = s_cnt[c * NBINS + bi];
            s_cnt[c * NBINS + bi] = (unsigned char)run;
            run += v;
        }
    }
    __syncthreads();

    // parallel deterministic scatter
    for (int i = tid; i < N_CONST; i += 1024) {
        float4 p = s_pts[i];
        int bi = bin_of(p.x);
        int pos = s_base[bi] + (int)s_cnt[(i >> 5) * NBINS + bi] + (int)s_rank[i];
        g_sorted[cloud * N_CONST + pos] = p;
        g_sidx[cloud * N_CONST + pos] = i;
    }
}

// Packed body (QPT=2), bit-exact with rescan.
#define NN_BODY(G)                                                              \
    {                                                                           \
        const float* gb = s_tile + (G) * (JPG * 8);                             \
        float mE0 = CUDART_INF_F, mO0 = CUDART_INF_F;                           \
        float mE1 = CUDART_INF_F, mO1 = CUDART_INF_F;                           \
        _Pragma("unroll")                                                       \
        for (int jj = 0; jj < JPG; jj++) {                                      \
            ulonglong2 A  = *(const ulonglong2*)(gb + jj * 8);                  \
            ulonglong2 Bv = *(const ulonglong2*)(gb + jj * 8 + 4);              \
            float tlo, thi;                                                     \
            asm("{\n\t.reg .b64 t;\n\t"                                         \
                "fma.rn.f32x2 t, %2, %3, %4;\n\t"                               \
                "fma.rn.f32x2 t, %5, %6, t;\n\t"                                \
                "fma.rn.f32x2 t, %7, %8, t;\n\t"                                \
                "mov.b64 {%0, %1}, t;\n\t}"                                     \
                : "=f"(tlo), "=f"(thi)                                          \
                : "l"(qx2[0]), "l"(A.x), "l"(Bv.y),                             \
                  "l"(qy2[0]), "l"(A.y), "l"(qz2[0]), "l"(Bv.x));               \
            mE0 = fminf(mE0, tlo); mO0 = fminf(mO0, thi);                       \
            asm("{\n\t.reg .b64 t;\n\t"                                         \
                "fma.rn.f32x2 t, %2, %3, %4;\n\t"                               \
                "fma.rn.f32x2 t, %5, %6, t;\n\t"                                \
                "fma.rn.f32x2 t, %7, %8, t;\n\t"                                \
                "mov.b64 {%0, %1}, t;\n\t}"                                     \
                : "=f"(tlo), "=f"(thi)                                          \
                : "l"(qx2[1]), "l"(A.x), "l"(Bv.y),                             \
                  "l"(qy2[1]), "l"(A.y), "l"(qz2[1]), "l"(Bv.x));               \
            mE1 = fminf(mE1, tlo); mO1 = fminf(mO1, thi);                       \
        }                                                                       \
        float m0 = fminf(mE0, mO0);                                             \
        if (m0 < best[0]) { best[0] = m0; gidw[0] = (G); bestd[0] = m0 + cc[0]; } \
        float m1 = fminf(mE1, mO1);                                             \
        if (m1 < best[1]) { best[1] = m1; gidw[1] = (G); bestd[1] = m1 + cc[1]; } \
    }

// db = dir*B + b.  dir 0: queries = gts, refs = preds. dir 1: swapped.
__global__ __launch_bounds__(TPB, 1) void nn_kernel() {
    extern __shared__ float sm[];
    float* s_tile = sm;                         // 32768 floats, jj-interleaved
    int*   s_sidx = (int*)(sm + 32768);         // 8192 orig indices
    float* s_gmin = sm + 32768 + 8192;          // 256 true group min x
    float* s_gmax = s_gmin + NGROUPS;           // 256 true group max x
    float* s_suf  = s_gmax + NGROUPS;           // 256 suffix-min of gmin (monotone)
    float* s_pmax = s_suf + NGROUPS;            // 256 prefix-max of gmax (monotone)

    const int tid = threadIdx.x;
    const int db  = blockIdx.y;
    const int b   = db & 3;
    const int dir = db >> 2;
    const int qc  = (dir == 0) ? b : 4 + b;
    const int rc  = (dir == 0) ? 4 + b : b;
    const float4* gr  = g_sorted + rc * N_CONST;
    const int*    gri = g_sidx   + rc * N_CONST;
    const float4* gq  = g_sorted + qc * N_CONST;
    const int*    gqi = g_sidx   + qc * N_CONST;

    for (int j = tid; j < N_CONST; j += TPB) {
        float4 p = gr[j];
        int jj = j >> 1, h = j & 1;
        float* pp = s_tile + jj * 8;
        pp[0 + h] = p.x; pp[2 + h] = p.y; pp[4 + h] = p.z; pp[6 + h] = p.w;
        s_sidx[j] = gri[j];
    }
    __syncthreads();
    // true group bounds (bin-sort leaves within-bin disorder)
    {
        float lo = CUDART_INF_F, hi = -CUDART_INF_F;
        #pragma unroll 8
        for (int j = 0; j < GROUP; j++) {
            int pos = tid * GROUP + j;
            float x = s_tile[(pos >> 1) * 8 + (pos & 1)];
            lo = fminf(lo, x); hi = fmaxf(hi, x);
        }
        s_gmin[tid] = lo; s_gmax[tid] = hi;
        s_suf[tid] = lo;  s_pmax[tid] = hi;
    }
    __syncthreads();
    // Hillis-Steele: suffix-min of gmin, prefix-max of gmax (both monotone)
    for (int st = 1; st < NGROUPS; st <<= 1) {
        float a = (tid + st < NGROUPS) ? s_suf[tid + st] : CUDART_INF_F;
        float c2 = (tid >= st) ? s_pmax[tid - st] : -CUDART_INF_F;
        __syncthreads();
        s_suf[tid] = fminf(s_suf[tid], a);
        s_pmax[tid] = fmaxf(s_pmax[tid], c2);
        __syncthreads();
    }

    float qx[QPT], cc[QPT], qxs[QPT], qys[QPT], qzs[QPT];
    unsigned long long qx2[QPT], qy2[QPT], qz2[QPT];
    float best[QPT], bestd[QPT];
    int gidw[QPT], oq[QPT];

    #pragma unroll
    for (int k = 0; k < QPT; k++) {
        int qpos = blockIdx.x * QPC + tid * QPT + k;   // warp: 64 sorted-adjacent
        float4 qp = gq[qpos];
        oq[k] = gqi[qpos];
        qx[k] = qp.x; cc[k] = qp.w;
        qxs[k] = -2.0f * qp.x; qys[k] = -2.0f * qp.y; qzs[k] = -2.0f * qp.z;
        asm("mov.b64 %0, {%1, %1};" : "=l"(qx2[k]) : "f"(qxs[k]));
        asm("mov.b64 %0, {%1, %1};" : "=l"(qy2[k]) : "f"(qys[k]));
        asm("mov.b64 %0, {%1, %1};" : "=l"(qz2[k]) : "f"(qzs[k]));
        best[k] = CUDART_INF_F; bestd[k] = CUDART_INF_F; gidw[k] = 0;
    }

    // home seed via binary search on monotone s_suf (any seed is correct;
    // exactness comes from the envelope-tested sweeps)
    int ghome[QPT];
    #pragma unroll
    for (int k = 0; k < QPT; k++) {
        int lo = 0, hi = NGROUPS - 1;
        #pragma unroll
        for (int it = 0; it < 8; it++) {
            int mid = (lo + hi + 1) >> 1;
            if (s_suf[mid] <= qx[k]) lo = mid; else hi = mid - 1;
        }
        ghome[k] = lo;
    }
    int gmn = min(ghome[0], ghome[1]);
    int gmx = max(ghome[0], ghome[1]);
    #pragma unroll
    for (int o = 16; o; o >>= 1) {
        gmn = min(gmn, __shfl_xor_sync(0xffffffffu, gmn, o));
        gmx = max(gmx, __shfl_xor_sync(0xffffffffu, gmx, o));
    }
    for (int g = gmn; g <= gmx; g++) NN_BODY(g);

    // right sweep: envelope s_suf exact break; per-group s_gmin exact skip
    for (int g = gmx + 1; g < NGROUPS; g++) {
        float e0 = fmaxf(s_suf[g] - qx[0], 0.0f);
        float e1 = fmaxf(s_suf[g] - qx[1], 0.0f);
        bool live = (e0 * e0 <= bestd[0] * 1.000002f + 1e-7f)
                 || (e1 * e1 <= bestd[1] * 1.000002f + 1e-7f);
        if (!__any_sync(0xffffffffu, live)) break;
        float f0 = fmaxf(s_gmin[g] - qx[0], 0.0f);
        float f1 = fmaxf(s_gmin[g] - qx[1], 0.0f);
        bool need = (f0 * f0 <= bestd[0] * 1.000002f + 1e-7f)
                 || (f1 * f1 <= bestd[1] * 1.000002f + 1e-7f);
        if (!__any_sync(0xffffffffu, need)) continue;
        NN_BODY(g);
    }
    // left sweep: envelope s_pmax exact break; per-group s_gmax exact skip
    for (int g = gmn - 1; g >= 0; g--) {
        float e0 = fmaxf(qx[0] - s_pmax[g], 0.0f);
        float e1 = fmaxf(qx[1] - s_pmax[g], 0.0f);
        bool live = (e0 * e0 <= bestd[0] * 1.000002f + 1e-7f)
                 || (e1 * e1 <= bestd[1] * 1.000002f + 1e-7f);
        if (!__any_sync(0xffffffffu, live)) break;
        float f0 = fmaxf(qx[0] - s_gmax[g], 0.0f);
        float f1 = fmaxf(qx[1] - s_gmax[g], 0.0f);
        bool need = (f0 * f0 <= bestd[0] * 1.000002f + 1e-7f)
                 || (f1 * f1 <= bestd[1] * 1.000002f + 1e-7f);
        if (!__any_sync(0xffffffffu, need)) continue;
        NN_BODY(g);
    }

    // rescan winning group: bit-exact recompute, min ORIGINAL index among ties
    #pragma unroll
    for (int k = 0; k < QPT; k++) {
        const int base = gidw[k] * GROUP;
        int bi = 0x7fffffff;
        #pragma unroll 8
        for (int j = 0; j < GROUP; j++) {
            int pos = base + j;
            const float* p = s_tile + (pos >> 1) * 8;
            int h = pos & 1;
            float t = fmaf(qxs[k], p[0 + h], p[6 + h]);
            t = fmaf(qys[k], p[2 + h], t);
            t = fmaf(qzs[k], p[4 + h], t);
            if (t == best[k]) bi = min(bi, s_sidx[pos]);
        }
        g_idx[db * N_CONST + oq[k]] = bi;
        atomicAdd(&g_cnt[db * N_CONST + bi], 1);
    }
}

// One CTA per b: both dirs, deterministic tree reduce -> out[b]
__global__ __launch_bounds__(1024) void finalize_kernel(const float* __restrict__ gts,
                                                        const float* __restrict__ preds,
                                                        float* __restrict__ out) {
    __shared__ float ssum[1024];
    const int b = blockIdx.x;
    const int tid = threadIdx.x;
    float acc = 0.0f;

    #pragma unroll
    for (int dir = 0; dir < 2; dir++) {
        const int db = dir * B_CONST + b;
        const float* qptr = (dir == 0) ? gts : preds;
        const float* rptr = (dir == 0) ? preds : gts;
        const float* qb = qptr + (long)b * N_CONST * 3;
        const float* rb = rptr + (long)b * N_CONST * 3;
        #pragma unroll
        for (int i = 0; i < N_CONST / 1024; i++) {
            int q = tid + i * 1024;
            int id = g_idx[db * N_CONST + q];
            float dx = qb[3 * q + 0] - rb[3 * id + 0];
            float dy = qb[3 * q + 1] - rb[3 * id + 1];
            float dz = qb[3 * q + 2] - rb[3 * id + 2];
            float d  = dx * dx + dy * dy + dz * dz;
            float c  = (float)g_cnt[db * N_CONST + id];
            acc += 1.0f - expf(-d) / (c + 1e-6f);   // ALPHA=1, N_LAMBDA=1, frac=1
        }
    }

    ssum[tid] = acc;
    __syncthreads();
    for (int off = 512; off > 0; off >>= 1) {
        if (tid < off) ssum[tid] += ssum[tid + off];
        __syncthreads();
    }
    if (tid == 0) out[b] = ssum[0] / (2.0f * (float)N_CONST);
}

extern "C" void kernel_launch(void* const* d_in, const int* in_sizes, int n_in,
                              void* d_out, int out_size) {
    const float* gts   = (const float*)d_in[0];
    const float* preds = (const float*)d_in[1];
    float* out = (float*)d_out;

    cudaFuncSetAttribute(sort_kernel, cudaFuncAttributeMaxDynamicSharedMemorySize, SORT_SMEM);
    cudaFuncSetAttribute(nn_kernel, cudaFuncAttributeMaxDynamicSharedMemorySize, NN_SMEM);

    sort_kernel<<<NCLOUD, 1024, SORT_SMEM>>>(gts, preds);
    nn_kernel<<<dim3(QCHUNKS, 2 * B_CONST), TPB, NN_SMEM>>>();
    finalize_kernel<<<B_CONST, 1024>>>(gts, preds, out);
}

// round 14
// speedup vs baseline: 1.1851x; 1.0714x over previous
#include <cuda_runtime.h>
#include <math_constants.h>

// Density-aware Chamfer loss, B=4, N=8192, 3D fp32.
// R14 = R13 sort + R11 nn (sampled bounds, single vote) with GROUP=16 +
// R12 fused finalize. 3 launches.

#define B_CONST   4
#define N_CONST   8192
#define NCLOUD    8
#define NBINS     256
#define NCHUNKS   (N_CONST / 32)       // 256
#define CPQ       (NCHUNKS / 4)        // 64

#define TPB       256
#define QPT       2
#define QPC       (TPB * QPT)          // 512 queries / CTA
#define QCHUNKS   (N_CONST / QPC)      // 16
#define GROUP     16
#define JPG       (GROUP / 2)          // 8
#define NGROUPS   (N_CONST / GROUP)    // 512

#define SORT_SMEM (131072 + 65536 + 8192 + 4096 + 1024 + 1024)   // 210944
#define NN_SMEM   ((32768 + 8192 + 2 * NGROUPS) * 4)             // 167936

__device__ float4 g_sorted[NCLOUD * N_CONST];
__device__ int    g_sidx  [NCLOUD * N_CONST];
__device__ int    g_idx   [2 * B_CONST * N_CONST];
__device__ int    g_cnt   [2 * B_CONST * N_CONST];

__device__ __forceinline__ int bin_of(float x) {
    int bi = (int)floorf((x + 5.2f) * (256.0f / 10.4f));
    return min(max(bi, 0), NBINS - 1);
}

// cloud 0..3 = gts[b], cloud 4..7 = preds[b]
__global__ __launch_bounds__(1024, 1) void sort_kernel(const float* __restrict__ gts,
                                                       const float* __restrict__ preds) {
    extern __shared__ char sm_raw[];
    float4*        s_pts  = (float4*)sm_raw;                            // [8192]
    unsigned char* s_cnt  = (unsigned char*)(sm_raw + 131072);          // [chunk][bin]
    unsigned char* s_rank = (unsigned char*)(sm_raw + 131072 + 65536);  // [8192]
    int*           s_qsum = (int*)(sm_raw + 131072 + 65536 + 8192);     // [4][256]
    int*           s_hist = s_qsum + 4 * NBINS;                         // [256]
    int*           s_base = s_hist + NBINS;                             // [256]

    const int tid   = threadIdx.x;
    const int cloud = blockIdx.x;
    const float* src = (cloud < 4) ? gts + (long)cloud * N_CONST * 3
                                   : preds + (long)(cloud - 4) * N_CONST * 3;

    for (int i = tid; i < N_CONST; i += 1024) g_cnt[cloud * N_CONST + i] = 0;
    for (int i = tid; i < (NCHUNKS * NBINS) / 4; i += 1024) ((int*)s_cnt)[i] = 0;
    for (int i = tid; i < N_CONST; i += 1024) {
        float x = src[3 * i], y = src[3 * i + 1], z = src[3 * i + 2];
        s_pts[i] = make_float4(x, y, z, x * x + y * y + z * z);
    }
    __syncthreads();

    {
        const int w = tid >> 5, lane = tid & 31;
        #pragma unroll
        for (int cc = 0; cc < NCHUNKS / 32; cc++) {
            int c = w * (NCHUNKS / 32) + cc;
            int i = c * 32 + lane;
            int bi = bin_of(s_pts[i].x);
            unsigned mask = __match_any_sync(0xffffffffu, bi);
            s_rank[i] = (unsigned char)__popc(mask & ((1u << lane) - 1u));
            if ((int)(__ffs(mask) - 1) == lane)
                s_cnt[c * NBINS + bi] = (unsigned char)__popc(mask);
        }
    }
    __syncthreads();

    {
        const int bi = tid & (NBINS - 1);
        const int qt = tid >> 8;
        int run = 0;
        #pragma unroll 8
        for (int c = qt * CPQ; c < (qt + 1) * CPQ; c++)
            run += s_cnt[c * NBINS + bi];
        s_qsum[qt * NBINS + bi] = run;
    }
    __syncthreads();

    if (tid < NBINS) {
        int r0 = 0;
        #pragma unroll
        for (int qt = 0; qt < 4; qt++) {
            int v = s_qsum[qt * NBINS + tid];
            s_qsum[qt * NBINS + tid] = r0;
            r0 += v;
        }
        s_hist[tid] = r0;
    }
    __syncthreads();

    if (tid < 32) {
        int lsum = 0;
        #pragma unroll
        for (int j = 0; j < 8; j++) lsum += s_hist[tid * 8 + j];
        int excl = lsum;
        #pragma unroll
        for (int o = 1; o < 32; o <<= 1) {
            int v = __shfl_up_sync(0xffffffffu, excl, o);
            if ((tid & 31) >= o) excl += v;
        }
        excl -= lsum;
        int run = excl;
        #pragma unroll
        for (int j = 0; j < 8; j++) {
            s_base[tid * 8 + j] = run;
            run += s_hist[tid * 8 + j];
        }
    }
    __syncthreads();

    {
        const int bi = tid & (NBINS - 1);
        const int qt = tid >> 8;
        int run = s_qsum[qt * NBINS + bi];
        #pragma unroll 8
        for (int c = qt * CPQ; c < (qt + 1) * CPQ; c++) {
            int v = s_cnt[c * NBINS + bi];
            s_cnt[c * NBINS + bi] = (unsigned char)run;
            run += v;
        }
    }
    __syncthreads();

    for (int i = tid; i < N_CONST; i += 1024) {
        float4 p = s_pts[i];
        int bi = bin_of(p.x);
        int pos = s_base[bi] + (int)s_cnt[(i >> 5) * NBINS + bi] + (int)s_rank[i];
        g_sorted[cloud * N_CONST + pos] = p;
        g_sidx[cloud * N_CONST + pos] = i;
    }
}

// Packed body (QPT=2, GROUP=16 => 8 j-pairs), bit-exact with rescan.
#define NN_BODY(G)                                                              \
    {                                                                           \
        const float* gb = s_tile + (G) * (JPG * 8);                             \
        float mE0 = CUDART_INF_F, mO0 = CUDART_INF_F;                           \
        float mE1 = CUDART_INF_F, mO1 = CUDART_INF_F;                           \
        _Pragma("unroll")                                                       \
        for (int jj = 0; jj < JPG; jj++) {                                      \
            ulonglong2 A  = *(const ulonglong2*)(gb + jj * 8);                  \
            ulonglong2 Bv = *(const ulonglong2*)(gb + jj * 8 + 4);              \
            float tlo, thi;                                                     \
            asm("{\n\t.reg .b64 t;\n\t"                                         \
                "fma.rn.f32x2 t, %2, %3, %4;\n\t"                               \
                "fma.rn.f32x2 t, %5, %6, t;\n\t"                                \
                "fma.rn.f32x2 t, %7, %8, t;\n\t"                                \
                "mov.b64 {%0, %1}, t;\n\t}"                                     \
                : "=f"(tlo), "=f"(thi)                                          \
                : "l"(qx2[0]), "l"(A.x), "l"(Bv.y),                             \
                  "l"(qy2[0]), "l"(A.y), "l"(qz2[0]), "l"(Bv.x));               \
            mE0 = fminf(mE0, tlo); mO0 = fminf(mO0, thi);                       \
            asm("{\n\t.reg .b64 t;\n\t"                                         \
                "fma.rn.f32x2 t, %2, %3, %4;\n\t"                               \
                "fma.rn.f32x2 t, %5, %6, t;\n\t"                                \
                "fma.rn.f32x2 t, %7, %8, t;\n\t"                                \
                "mov.b64 {%0, %1}, t;\n\t}"                                     \
                : "=f"(tlo), "=f"(thi)                                          \
                : "l"(qx2[1]), "l"(A.x), "l"(Bv.y),                             \
                  "l"(qy2[1]), "l"(A.y), "l"(qz2[1]), "l"(Bv.x));               \
            mE1 = fminf(mE1, tlo); mO1 = fminf(mO1, thi);                       \
        }                                                                       \
        float m0 = fminf(mE0, mO0);                                             \
        if (m0 < best[0]) { best[0] = m0; gidw[0] = (G); bestd[0] = m0 + cc[0]; } \
        float m1 = fminf(mE1, mO1);                                             \
        if (m1 < best[1]) { best[1] = m1; gidw[1] = (G); bestd[1] = m1 + cc[1]; } \
    }

// db = dir*B + b.  dir 0: queries = gts, refs = preds. dir 1: swapped.
__global__ __launch_bounds__(TPB, 1) void nn_kernel() {
    extern __shared__ float sm[];
    float* s_tile = sm;                         // 32768 floats, jj-interleaved
    int*   s_sidx = (int*)(sm + 32768);         // 8192 orig indices
    float* s_glo  = sm + 32768 + 8192;          // 512 sampled group lo x
    float* s_ghi  = s_glo + NGROUPS;            // 512 sampled group hi x

    const int tid = threadIdx.x;
    const int db  = blockIdx.y;
    const int b   = db & 3;
    const int dir = db >> 2;
    const int qc  = (dir == 0) ? b : 4 + b;
    const int rc  = (dir == 0) ? 4 + b : b;
    const float4* gr  = g_sorted + rc * N_CONST;
    const int*    gri = g_sidx   + rc * N_CONST;
    const float4* gq  = g_sorted + qc * N_CONST;
    const int*    gqi = g_sidx   + qc * N_CONST;

    for (int j = tid; j < N_CONST; j += TPB) {
        float4 p = gr[j];
        int jj = j >> 1, h = j & 1;
        float* pp = s_tile + jj * 8;
        pp[0 + h] = p.x; pp[2 + h] = p.y; pp[4 + h] = p.z; pp[6 + h] = p.w;
        s_sidx[j] = gri[j];
    }
    __syncthreads();
    // sampled group bounds (R11 style): glo=x[16g], ghi=x[16g+15]; 2 groups/thread
    #pragma unroll
    for (int r = 0; r < NGROUPS / TPB; r++) {
        int g = tid + r * TPB;
        int p0 = g * GROUP, p1 = g * GROUP + GROUP - 1;
        s_glo[g] = s_tile[(p0 >> 1) * 8 + (p0 & 1)];
        s_ghi[g] = s_tile[(p1 >> 1) * 8 + (p1 & 1)];
    }
    __syncthreads();

    float qx[QPT], cc[QPT], qxs[QPT], qys[QPT], qzs[QPT];
    unsigned long long qx2[QPT], qy2[QPT], qz2[QPT];
    float best[QPT], bestd[QPT];
    int gidw[QPT], oq[QPT], ghome[QPT];

    #pragma unroll
    for (int k = 0; k < QPT; k++) {
        int qpos = blockIdx.x * QPC + tid * QPT + k;   // warp: 64 sorted-adjacent
        float4 qp = gq[qpos];
        oq[k] = gqi[qpos];
        qx[k] = qp.x; cc[k] = qp.w;
        qxs[k] = -2.0f * qp.x; qys[k] = -2.0f * qp.y; qzs[k] = -2.0f * qp.z;
        asm("mov.b64 %0, {%1, %1};" : "=l"(qx2[k]) : "f"(qxs[k]));
        asm("mov.b64 %0, {%1, %1};" : "=l"(qy2[k]) : "f"(qys[k]));
        asm("mov.b64 %0, {%1, %1};" : "=l"(qz2[k]) : "f"(qzs[k]));
        best[k] = CUDART_INF_F; bestd[k] = CUDART_INF_F; gidw[k] = 0;
        int lo = 0, hi = NGROUPS - 1;
        #pragma unroll
        for (int it = 0; it < 9; it++) {
            int mid = (lo + hi + 1) >> 1;
            if (s_glo[mid] <= qx[k]) lo = mid; else hi = mid - 1;
        }
        ghome[k] = lo;
    }

    int gmn = min(ghome[0], ghome[1]);
    int gmx = max(ghome[0], ghome[1]);
    #pragma unroll
    for (int o = 16; o; o >>= 1) {
        gmn = min(gmn, __shfl_xor_sync(0xffffffffu, gmn, o));
        gmx = max(gmx, __shfl_xor_sync(0xffffffffu, gmx, o));
    }
    for (int g = gmn; g <= gmx; g++) NN_BODY(g);

    // right sweep
    for (int g = gmx + 1; g < NGROUPS; g++) {
        float e0 = s_glo[g] - qx[0];
        float e1 = s_glo[g] - qx[1];
        bool need = (e0 * e0 <= bestd[0] * 1.000002f + 1e-7f)
                 || (e1 * e1 <= bestd[1] * 1.000002f + 1e-7f);
        if (!__any_sync(0xffffffffu, need)) break;
        NN_BODY(g);
    }
    // left sweep
    for (int g = gmn - 1; g >= 0; g--) {
        float e0 = qx[0] - s_ghi[g];
        float e1 = qx[1] - s_ghi[g];
        bool need = (e0 * e0 <= bestd[0] * 1.000002f + 1e-7f)
                 || (e1 * e1 <= bestd[1] * 1.000002f + 1e-7f);
        if (!__any_sync(0xffffffffu, need)) break;
        NN_BODY(g);
    }

    // rescan winning group: bit-exact recompute, min ORIGINAL index among ties
    #pragma unroll
    for (int k = 0; k < QPT; k++) {
        const int base = gidw[k] * GROUP;
        int bi = 0x7fffffff;
        #pragma unroll
        for (int j = 0; j < GROUP; j++) {
            int pos = base + j;
            const float* p = s_tile + (pos >> 1) * 8;
            int h = pos & 1;
            float t = fmaf(qxs[k], p[0 + h], p[6 + h]);
            t = fmaf(qys[k], p[2 + h], t);
            t = fmaf(qzs[k], p[4 + h], t);
            if (t == best[k]) bi = min(bi, s_sidx[pos]);
        }
        g_idx[db * N_CONST + oq[k]] = bi;
        atomicAdd(&g_cnt[db * N_CONST + bi], 1);
    }
}

// One CTA per b: both dirs, deterministic tree reduce -> out[b]
__global__ __launch_bounds__(1024) void finalize_kernel(const float* __restrict__ gts,
                                                        const float* __restrict__ preds,
                                                        float* __restrict__ out) {
    __shared__ float ssum[1024];
    const int b = blockIdx.x;
    const int tid = threadIdx.x;
    float acc = 0.0f;

    #pragma unroll
    for (int dir = 0; dir < 2; dir++) {
        const int db = dir * B_CONST + b;
        const float* qptr = (dir == 0) ? gts : preds;
        const float* rptr = (dir == 0) ? preds : gts;
        const float* qb = qptr + (long)b * N_CONST * 3;
        const float* rb = rptr + (long)b * N_CONST * 3;
        #pragma unroll
        for (int i = 0; i < N_CONST / 1024; i++) {
            int q = tid + i * 1024;
            int id = g_idx[db * N_CONST + q];
            float dx = qb[3 * q + 0] - rb[3 * id + 0];
            float dy = qb[3 * q + 1] - rb[3 * id + 1];
            float dz = qb[3 * q + 2] - rb[3 * id + 2];
            float d  = dx * dx + dy * dy + dz * dz;
            float c  = (float)g_cnt[db * N_CONST + id];
            acc += 1.0f - expf(-d) / (c + 1e-6f);   // ALPHA=1, N_LAMBDA=1, frac=1
        }
    }

    ssum[tid] = acc;
    __syncthreads();
    for (int off = 512; off > 0; off >>= 1) {
        if (tid < off) ssum[tid] += ssum[tid + off];
        __syncthreads();
    }
    if (tid == 0) out[b] = ssum[0] / (2.0f * (float)N_CONST);
}

extern "C" void kernel_launch(void* const* d_in, const int* in_sizes, int n_in,
                              void* d_out, int out_size) {
    const float* gts   = (const float*)d_in[0];
    const float* preds = (const float*)d_in[1];
    float* out = (float*)d_out;

    cudaFuncSetAttribute(sort_kernel, cudaFuncAttributeMaxDynamicSharedMemorySize, SORT_SMEM);
    cudaFuncSetAttribute(nn_kernel, cudaFuncAttributeMaxDynamicSharedMemorySize, NN_SMEM);

    sort_kernel<<<NCLOUD, 1024, SORT_SMEM>>>(gts, preds);
    nn_kernel<<<dim3(QCHUNKS, 2 * B_CONST), TPB, NN_SMEM>>>();
    finalize_kernel<<<B_CONST, 1024>>>(gts, preds, out);
}

// round 15
// speedup vs baseline: 1.2698x; 1.0715x over previous
#include <cuda_runtime.h>
#include <math_constants.h>

// Density-aware Chamfer loss, B=4, N=8192, 3D fp32.
// R15 = best-of-breed assembly: R13 sort (28.5us) + R11 nn verbatim (~71us,
// GROUP=32, sampled bounds, single vote) + R12 fused finalize (~5us).
// 3 launches.

#define B_CONST   4
#define N_CONST   8192
#define NCLOUD    8
#define NBINS     256
#define NCHUNKS   (N_CONST / 32)       // 256
#define CPQ       (NCHUNKS / 4)        // 64

#define TPB       256
#define QPT       2
#define QPC       (TPB * QPT)          // 512 queries / CTA
#define QCHUNKS   (N_CONST / QPC)      // 16
#define GROUP     32
#define JPG       (GROUP / 2)          // 16
#define NGROUPS   (N_CONST / GROUP)    // 256

#define SORT_SMEM (131072 + 65536 + 8192 + 4096 + 1024 + 1024)   // 210944
#define NN_SMEM   ((32768 + 8192 + 256 + 256) * 4)               // 165888

__device__ float4 g_sorted[NCLOUD * N_CONST];
__device__ int    g_sidx  [NCLOUD * N_CONST];
__device__ int    g_idx   [2 * B_CONST * N_CONST];
__device__ int    g_cnt   [2 * B_CONST * N_CONST];

__device__ __forceinline__ int bin_of(float x) {
    int bi = (int)floorf((x + 5.2f) * (256.0f / 10.4f));
    return min(max(bi, 0), NBINS - 1);
}

// cloud 0..3 = gts[b], cloud 4..7 = preds[b]
__global__ __launch_bounds__(1024, 1) void sort_kernel(const float* __restrict__ gts,
                                                       const float* __restrict__ preds) {
    extern __shared__ char sm_raw[];
    float4*        s_pts  = (float4*)sm_raw;                            // [8192]
    unsigned char* s_cnt  = (unsigned char*)(sm_raw + 131072);          // [chunk][bin]
    unsigned char* s_rank = (unsigned char*)(sm_raw + 131072 + 65536);  // [8192]
    int*           s_qsum = (int*)(sm_raw + 131072 + 65536 + 8192);     // [4][256]
    int*           s_hist = s_qsum + 4 * NBINS;                         // [256]
    int*           s_base = s_hist + NBINS;                             // [256]

    const int tid   = threadIdx.x;
    const int cloud = blockIdx.x;
    const float* src = (cloud < 4) ? gts + (long)cloud * N_CONST * 3
                                   : preds + (long)(cloud - 4) * N_CONST * 3;

    for (int i = tid; i < N_CONST; i += 1024) g_cnt[cloud * N_CONST + i] = 0;
    for (int i = tid; i < (NCHUNKS * NBINS) / 4; i += 1024) ((int*)s_cnt)[i] = 0;
    for (int i = tid; i < N_CONST; i += 1024) {
        float x = src[3 * i], y = src[3 * i + 1], z = src[3 * i + 2];
        s_pts[i] = make_float4(x, y, z, x * x + y * y + z * z);
    }
    __syncthreads();

    {
        const int w = tid >> 5, lane = tid & 31;
        #pragma unroll
        for (int cc = 0; cc < NCHUNKS / 32; cc++) {
            int c = w * (NCHUNKS / 32) + cc;
            int i = c * 32 + lane;
            int bi = bin_of(s_pts[i].x);
            unsigned mask = __match_any_sync(0xffffffffu, bi);
            s_rank[i] = (unsigned char)__popc(mask & ((1u << lane) - 1u));
            if ((int)(__ffs(mask) - 1) == lane)
                s_cnt[c * NBINS + bi] = (unsigned char)__popc(mask);
        }
    }
    __syncthreads();

    {
        const int bi = tid & (NBINS - 1);
        const int qt = tid >> 8;
        int run = 0;
        #pragma unroll 8
        for (int c = qt * CPQ; c < (qt + 1) * CPQ; c++)
            run += s_cnt[c * NBINS + bi];
        s_qsum[qt * NBINS + bi] = run;
    }
    __syncthreads();

    if (tid < NBINS) {
        int r0 = 0;
        #pragma unroll
        for (int qt = 0; qt < 4; qt++) {
            int v = s_qsum[qt * NBINS + tid];
            s_qsum[qt * NBINS + tid] = r0;
            r0 += v;
        }
        s_hist[tid] = r0;
    }
    __syncthreads();

    if (tid < 32) {
        int lsum = 0;
        #pragma unroll
        for (int j = 0; j < 8; j++) lsum += s_hist[tid * 8 + j];
        int excl = lsum;
        #pragma unroll
        for (int o = 1; o < 32; o <<= 1) {
            int v = __shfl_up_sync(0xffffffffu, excl, o);
            if ((tid & 31) >= o) excl += v;
        }
        excl -= lsum;
        int run = excl;
        #pragma unroll
        for (int j = 0; j < 8; j++) {
            s_base[tid * 8 + j] = run;
            run += s_hist[tid * 8 + j];
        }
    }
    __syncthreads();

    {
        const int bi = tid & (NBINS - 1);
        const int qt = tid >> 8;
        int run = s_qsum[qt * NBINS + bi];
        #pragma unroll 8
        for (int c = qt * CPQ; c < (qt + 1) * CPQ; c++) {
            int v = s_cnt[c * NBINS + bi];
            s_cnt[c * NBINS + bi] = (unsigned char)run;
            run += v;
        }
    }
    __syncthreads();

    for (int i = tid; i < N_CONST; i += 1024) {
        float4 p = s_pts[i];
        int bi = bin_of(p.x);
        int pos = s_base[bi] + (int)s_cnt[(i >> 5) * NBINS + bi] + (int)s_rank[i];
        g_sorted[cloud * N_CONST + pos] = p;
        g_sidx[cloud * N_CONST + pos] = i;
    }
}

// Packed body: identical math to R2 (bit-exact with rescan).  [R11 verbatim]
#define NN_BODY(G)                                                              \
    {                                                                           \
        const float* gb = s_tile + (G) * (JPG * 8);                             \
        float mE0 = CUDART_INF_F, mO0 = CUDART_INF_F;                           \
        float mE1 = CUDART_INF_F, mO1 = CUDART_INF_F;                           \
        _Pragma("unroll")                                                       \
        for (int jj = 0; jj < JPG; jj++) {                                      \
            ulonglong2 A  = *(const ulonglong2*)(gb + jj * 8);                  \
            ulonglong2 Bv = *(const ulonglong2*)(gb + jj * 8 + 4);              \
            float tlo, thi;                                                     \
            asm("{\n\t.reg .b64 t;\n\t"                                         \
                "fma.rn.f32x2 t, %2, %3, %4;\n\t"                               \
                "fma.rn.f32x2 t, %5, %6, t;\n\t"                                \
                "fma.rn.f32x2 t, %7, %8, t;\n\t"                                \
                "mov.b64 {%0, %1}, t;\n\t}"                                     \
                : "=f"(tlo), "=f"(thi)                                          \
                : "l"(qx2[0]), "l"(A.x), "l"(Bv.y),                             \
                  "l"(qy2[0]), "l"(A.y), "l"(qz2[0]), "l"(Bv.x));               \
            mE0 = fminf(mE0, tlo); mO0 = fminf(mO0, thi);                       \
            asm("{\n\t.reg .b64 t;\n\t"                                         \
                "fma.rn.f32x2 t, %2, %3, %4;\n\t"                               \
                "fma.rn.f32x2 t, %5, %6, t;\n\t"                                \
                "fma.rn.f32x2 t, %7, %8, t;\n\t"                                \
                "mov.b64 {%0, %1}, t;\n\t}"                                     \
                : "=f"(tlo), "=f"(thi)                                          \
                : "l"(qx2[1]), "l"(A.x), "l"(Bv.y),                             \
                  "l"(qy2[1]), "l"(A.y), "l"(qz2[1]), "l"(Bv.x));               \
            mE1 = fminf(mE1, tlo); mO1 = fminf(mO1, thi);                       \
        }                                                                       \
        float m0 = fminf(mE0, mO0);                                             \
        if (m0 < best[0]) { best[0] = m0; gidw[0] = (G); bestd[0] = m0 + cc[0]; } \
        float m1 = fminf(mE1, mO1);                                             \
        if (m1 < best[1]) { best[1] = m1; gidw[1] = (G); bestd[1] = m1 + cc[1]; } \
    }

// db = dir*B + b.  dir 0: queries = gts, refs = preds. dir 1: swapped.
__global__ __launch_bounds__(TPB, 1) void nn_kernel() {
    extern __shared__ float sm[];
    float* s_tile = sm;                         // 32768 floats, jj-interleaved
    int*   s_sidx = (int*)(sm + 32768);         // 8192 orig indices
    float* s_glo  = sm + 32768 + 8192;          // 256 sampled group lo x
    float* s_ghi  = s_glo + NGROUPS;            // 256 sampled group hi x

    const int tid = threadIdx.x;
    const int db  = blockIdx.y;
    const int b   = db & 3;
    const int dir = db >> 2;
    const int qc  = (dir == 0) ? b : 4 + b;
    const int rc  = (dir == 0) ? 4 + b : b;
    const float4* gr  = g_sorted + rc * N_CONST;
    const int*    gri = g_sidx   + rc * N_CONST;
    const float4* gq  = g_sorted + qc * N_CONST;
    const int*    gqi = g_sidx   + qc * N_CONST;

    for (int j = tid; j < N_CONST; j += TPB) {
        float4 p = gr[j];
        int jj = j >> 1, h = j & 1;
        float* pp = s_tile + jj * 8;
        pp[0 + h] = p.x; pp[2 + h] = p.y; pp[4 + h] = p.z; pp[6 + h] = p.w;
        s_sidx[j] = gri[j];
    }
    __syncthreads();
    if (tid < NGROUPS) {
        int p0 = tid * GROUP, p1 = tid * GROUP + GROUP - 1;
        s_glo[tid] = s_tile[(p0 >> 1) * 8 + (p0 & 1)];
        s_ghi[tid] = s_tile[(p1 >> 1) * 8 + (p1 & 1)];
    }
    __syncthreads();

    float qx[QPT], cc[QPT], qxs[QPT], qys[QPT], qzs[QPT];
    unsigned long long qx2[QPT], qy2[QPT], qz2[QPT];
    float best[QPT], bestd[QPT];
    int gidw[QPT], oq[QPT], ghome[QPT];

    #pragma unroll
    for (int k = 0; k < QPT; k++) {
        int qpos = blockIdx.x * QPC + tid * QPT + k;   // warp: 64 sorted-adjacent
        float4 qp = gq[qpos];
        oq[k] = gqi[qpos];
        qx[k] = qp.x; cc[k] = qp.w;
        qxs[k] = -2.0f * qp.x; qys[k] = -2.0f * qp.y; qzs[k] = -2.0f * qp.z;
        asm("mov.b64 %0, {%1, %1};" : "=l"(qx2[k]) : "f"(qxs[k]));
        asm("mov.b64 %0, {%1, %1};" : "=l"(qy2[k]) : "f"(qys[k]));
        asm("mov.b64 %0, {%1, %1};" : "=l"(qz2[k]) : "f"(qzs[k]));
        best[k] = CUDART_INF_F; bestd[k] = CUDART_INF_F; gidw[k] = 0;
        int lo = 0, hi = NGROUPS - 1;
        #pragma unroll
        for (int it = 0; it < 8; it++) {
            int mid = (lo + hi + 1) >> 1;
            if (s_glo[mid] <= qx[k]) lo = mid; else hi = mid - 1;
        }
        ghome[k] = lo;
    }

    int gmn = min(ghome[0], ghome[1]);
    int gmx = max(ghome[0], ghome[1]);
    #pragma unroll
    for (int o = 16; o; o >>= 1) {
        gmn = min(gmn, __shfl_xor_sync(0xffffffffu, gmn, o));
        gmx = max(gmx, __shfl_xor_sync(0xffffffffu, gmx, o));
    }
    for (int g = gmn; g <= gmx; g++) NN_BODY(g);

    // right sweep: first all-lane prune => early exit
    for (int g = gmx + 1; g < NGROUPS; g++) {
        float e0 = s_glo[g] - qx[0];
        float e1 = s_glo[g] - qx[1];
        bool need = (e0 * e0 <= bestd[0] * 1.000002f + 1e-7f)
                 || (e1 * e1 <= bestd[1] * 1.000002f + 1e-7f);
        if (!__any_sync(0xffffffffu, need)) break;
        NN_BODY(g);
    }
    // left sweep
    for (int g = gmn - 1; g >= 0; g--) {
        float e0 = qx[0] - s_ghi[g];
        float e1 = qx[1] - s_ghi[g];
        bool need = (e0 * e0 <= bestd[0] * 1.000002f + 1e-7f)
                 || (e1 * e1 <= bestd[1] * 1.000002f + 1e-7f);
        if (!__any_sync(0xffffffffu, need)) break;
        NN_BODY(g);
    }

    // rescan winning group: bit-exact recompute, min ORIGINAL index among ties
    #pragma unroll
    for (int k = 0; k < QPT; k++) {
        const int base = gidw[k] * GROUP;
        int bi = 0x7fffffff;
        #pragma unroll 8
        for (int j = 0; j < GROUP; j++) {
            int pos = base + j;
            const float* p = s_tile + (pos >> 1) * 8;
            int h = pos & 1;
            float t = fmaf(qxs[k], p[0 + h], p[6 + h]);
            t = fmaf(qys[k], p[2 + h], t);
            t = fmaf(qzs[k], p[4 + h], t);
            if (t == best[k]) bi = min(bi, s_sidx[pos]);
        }
        g_idx[db * N_CONST + oq[k]] = bi;
        atomicAdd(&g_cnt[db * N_CONST + bi], 1);
    }
}

// One CTA per b: both dirs, deterministic tree reduce -> out[b]
__global__ __launch_bounds__(1024) void finalize_kernel(const float* __restrict__ gts,
                                                        const float* __restrict__ preds,
                                                        float* __restrict__ out) {
    __shared__ float ssum[1024];
    const int b = blockIdx.x;
    const int tid = threadIdx.x;
    float acc = 0.0f;

    #pragma unroll
    for (int dir = 0; dir < 2; dir++) {
        const int db = dir * B_CONST + b;
        const float* qptr = (dir == 0) ? gts : preds;
        const float* rptr = (dir == 0) ? preds : gts;
        const float* qb = qptr + (long)b * N_CONST * 3;
        const float* rb = rptr + (long)b * N_CONST * 3;
        #pragma unroll
        for (int i = 0; i < N_CONST / 1024; i++) {
            int q = tid + i * 1024;
            int id = g_idx[db * N_CONST + q];
            float dx = qb[3 * q + 0] - rb[3 * id + 0];
            float dy = qb[3 * q + 1] - rb[3 * id + 1];
            float dz = qb[3 * q + 2] - rb[3 * id + 2];
            float d  = dx * dx + dy * dy + dz * dz;
            float c  = (float)g_cnt[db * N_CONST + id];
            acc += 1.0f - expf(-d) / (c + 1e-6f);   // ALPHA=1, N_LAMBDA=1, frac=1
        }
    }

    ssum[tid] = acc;
    __syncthreads();
    for (int off = 512; off > 0; off >>= 1) {
        if (tid < off) ssum[tid] += ssum[tid + off];
        __syncthreads();
    }
    if (tid == 0) out[b] = ssum[0] / (2.0f * (float)N_CONST);
}

extern "C" void kernel_launch(void* const* d_in, const int* in_sizes, int n_in,
                              void* d_out, int out_size) {
    const float* gts   = (const float*)d_in[0];
    const float* preds = (const float*)d_in[1];
    float* out = (float*)d_out;

    cudaFuncSetAttribute(sort_kernel, cudaFuncAttributeMaxDynamicSharedMemorySize, SORT_SMEM);
    cudaFuncSetAttribute(nn_kernel, cudaFuncAttributeMaxDynamicSharedMemorySize, NN_SMEM);

    sort_kernel<<<NCLOUD, 1024, SORT_SMEM>>>(gts, preds);
    nn_kernel<<<dim3(QCHUNKS, 2 * B_CONST), TPB, NN_SMEM>>>();
    finalize_kernel<<<B_CONST, 1024>>>(gts, preds, out);
}

// round 17
// speedup vs baseline: 1.5333x; 1.2075x over previous
#include <cuda_runtime.h>
#include <math_constants.h>

// Density-aware Chamfer loss, B=4, N=8192, 3D fp32.
// R17 = R16 with the sortA zero/write race fixed (missing __syncthreads()).
//  sortA : grid (8 seg, 8 cloud) x 256 — zero scratch, SYNC, then load pts,
//          bin, per-chunk match_any ranks + counts -> global scratch.
//  sortB : grid 8 x 1024 — per-cloud [chunk][bin] prefix in smem + bin bases.
//  sortC : grid (8,8) x 256 — parallel deterministic scatter.
//  nn    : R11 verbatim (GROUP=32, sampled bounds, single vote, bit-exact
//          winning-group rescan -> min ORIGINAL index; inline atomics).
//  finalize_partial (grid 256) + finalize_final (grid 1).

#define B_CONST   4
#define N_CONST   8192
#define NCLOUD    8
#define NBINS     256
#define NCHUNKS   (N_CONST / 32)       // 256 chunks per cloud
#define SEGS      8
#define PTS_SEG   (N_CONST / SEGS)     // 1024
#define CHK_SEG   (PTS_SEG / 32)       // 32 chunks per segment
#define CPQ       (NCHUNKS / 4)        // 64

#define TPB       256
#define QPT       2
#define QPC       (TPB * QPT)          // 512 queries / CTA
#define QCHUNKS   (N_CONST / QPC)      // 16
#define GROUP     32
#define JPG       (GROUP / 2)          // 16
#define NGROUPS   (N_CONST / GROUP)    // 256

#define FIN_TPB   256
#define FIN_BLOCKS (2 * B_CONST * N_CONST / FIN_TPB)  // 256
#define FIN_CPD   (N_CONST / FIN_TPB)                 // 32

#define SORTB_SMEM (65536 + 4096 + 1024 + 1024)       // 71680
#define NN_SMEM   ((32768 + 8192 + 256 + 256) * 4)    // 165888

__device__ float4        g_sorted[NCLOUD * N_CONST];
__device__ int           g_sidx  [NCLOUD * N_CONST];
__device__ float4        g_tpts  [NCLOUD * N_CONST];
__device__ unsigned char g_bin   [NCLOUD * N_CONST];
__device__ unsigned char g_rank  [NCLOUD * N_CONST];
__device__ unsigned char g_scnt  [NCLOUD * NCHUNKS * NBINS];  // 512KB
__device__ int           g_base  [NCLOUD * NBINS];
__device__ int           g_idx   [2 * B_CONST * N_CONST];
__device__ int           g_cnt   [2 * B_CONST * N_CONST];
__device__ float         g_part  [FIN_BLOCKS];

__device__ __forceinline__ int bin_of(float x) {
    int bi = (int)floorf((x + 5.2f) * (256.0f / 10.4f));
    return min(max(bi, 0), NBINS - 1);
}

// ---- Pass A: per-segment rank/count/bin.  grid (SEGS, NCLOUD) x 256 ----
__global__ __launch_bounds__(256) void sortA(const float* __restrict__ gts,
                                             const float* __restrict__ preds) {
    const int tid   = threadIdx.x;
    const int seg   = blockIdx.x;
    const int cloud = blockIdx.y;
    const int w     = tid >> 5, lane = tid & 31;
    const float* src = (cloud < 4) ? gts + (long)cloud * N_CONST * 3
                                   : preds + (long)(cloud - 4) * N_CONST * 3;

    // zero this segment's g_scnt rows (32 chunks x 256 bins = 8192B = 2048 u32)
    {
        unsigned* zp = (unsigned*)(g_scnt + (long)cloud * NCHUNKS * NBINS
                                          + (long)seg * CHK_SEG * NBINS);
        #pragma unroll
        for (int r = 0; r < 8; r++) zp[tid + r * 256] = 0u;
    }
    // zero g_cnt (65536 entries over 64 CTAs)
    {
        int base = (cloud * SEGS + seg) * 1024;
        #pragma unroll
        for (int r = 0; r < 4; r++) g_cnt[base + tid + r * 256] = 0;
    }
    __syncthreads();   // R16 BUG FIX: counts below must not race the zeroing above

    // 8 warps x 4 chunks each
    #pragma unroll
    for (int k = 0; k < 4; k++) {
        int c  = seg * CHK_SEG + w * 4 + k;     // chunk within cloud
        int i  = c * 32 + lane;                 // point within cloud
        float x = src[3 * i], y = src[3 * i + 1], z = src[3 * i + 2];
        g_tpts[cloud * N_CONST + i] = make_float4(x, y, z, x * x + y * y + z * z);
        int bi = bin_of(x);
        g_bin[cloud * N_CONST + i] = (unsigned char)bi;
        unsigned mask = __match_any_sync(0xffffffffu, bi);
        g_rank[cloud * N_CONST + i] = (unsigned char)__popc(mask & ((1u << lane) - 1u));
        if ((int)(__ffs(mask) - 1) == lane)
            g_scnt[(long)cloud * NCHUNKS * NBINS + c * NBINS + bi] =
                (unsigned char)__popc(mask);
    }
}

// ---- Pass B: per-cloud prefix over [chunk][bin] + bin bases.  grid 8 x 1024 ----
__global__ __launch_bounds__(1024, 1) void sortB() {
    extern __shared__ char sm_raw[];
    unsigned char* s_cnt  = (unsigned char*)sm_raw;            // [256][256]
    int*           s_qsum = (int*)(sm_raw + 65536);            // [4][256]
    int*           s_hist = s_qsum + 4 * NBINS;                // [256]
    int*           s_base = s_hist + NBINS;                    // [256]

    const int tid   = threadIdx.x;
    const int cloud = blockIdx.x;
    unsigned* gsc = (unsigned*)(g_scnt + (long)cloud * NCHUNKS * NBINS);

    #pragma unroll
    for (int r = 0; r < 16; r++)
        ((unsigned*)s_cnt)[tid + r * 1024] = gsc[tid + r * 1024];
    __syncthreads();

    {
        const int bi = tid & (NBINS - 1);
        const int qt = tid >> 8;
        int run = 0;
        #pragma unroll 8
        for (int c = qt * CPQ; c < (qt + 1) * CPQ; c++)
            run += s_cnt[c * NBINS + bi];
        s_qsum[qt * NBINS + bi] = run;
    }
    __syncthreads();

    if (tid < NBINS) {
        int r0 = 0;
        #pragma unroll
        for (int qt = 0; qt < 4; qt++) {
            int v = s_qsum[qt * NBINS + tid];
            s_qsum[qt * NBINS + tid] = r0;
            r0 += v;
        }
        s_hist[tid] = r0;
    }
    __syncthreads();

    if (tid < 32) {
        int lsum = 0;
        #pragma unroll
        for (int j = 0; j < 8; j++) lsum += s_hist[tid * 8 + j];
        int excl = lsum;
        #pragma unroll
        for (int o = 1; o < 32; o <<= 1) {
            int v = __shfl_up_sync(0xffffffffu, excl, o);
            if ((tid & 31) >= o) excl += v;
        }
        excl -= lsum;
        int run = excl;
        #pragma unroll
        for (int j = 0; j < 8; j++) {
            s_base[tid * 8 + j] = run;
            run += s_hist[tid * 8 + j];
        }
    }
    __syncthreads();

    {
        const int bi = tid & (NBINS - 1);
        const int qt = tid >> 8;
        int run = s_qsum[qt * NBINS + bi];
        #pragma unroll 8
        for (int c = qt * CPQ; c < (qt + 1) * CPQ; c++) {
            int v = s_cnt[c * NBINS + bi];
            s_cnt[c * NBINS + bi] = (unsigned char)run;
            run += v;
        }
    }
    __syncthreads();

    #pragma unroll
    for (int r = 0; r < 16; r++)
        gsc[tid + r * 1024] = ((unsigned*)s_cnt)[tid + r * 1024];
    if (tid < NBINS) g_base[cloud * NBINS + tid] = s_base[tid];
}

// ---- Pass C: deterministic scatter.  grid (SEGS, NCLOUD) x 256 ----
__global__ __launch_bounds__(256) void sortC() {
    const int tid   = threadIdx.x;
    const int seg   = blockIdx.x;
    const int cloud = blockIdx.y;

    #pragma unroll
    for (int r = 0; r < 4; r++) {
        int i = seg * PTS_SEG + r * 256 + tid;   // within cloud
        float4 p = g_tpts[cloud * N_CONST + i];
        int bi = (int)g_bin[cloud * N_CONST + i];
        int c  = i >> 5;
        int pos = g_base[cloud * NBINS + bi]
                + (int)g_scnt[(long)cloud * NCHUNKS * NBINS + c * NBINS + bi]
                + (int)g_rank[cloud * N_CONST + i];
        g_sorted[cloud * N_CONST + pos] = p;
        g_sidx[cloud * N_CONST + pos] = i;
    }
}

// Packed body: identical math to R2 (bit-exact with rescan).  [R11 verbatim]
#define NN_BODY(G)                                                              \
    {                                                                           \
        const float* gb = s_tile + (G) * (JPG * 8);                             \
        float mE0 = CUDART_INF_F, mO0 = CUDART_INF_F;                           \
        float mE1 = CUDART_INF_F, mO1 = CUDART_INF_F;                           \
        _Pragma("unroll")                                                       \
        for (int jj = 0; jj < JPG; jj++) {                                      \
            ulonglong2 A  = *(const ulonglong2*)(gb + jj * 8);                  \
            ulonglong2 Bv = *(const ulonglong2*)(gb + jj * 8 + 4);              \
            float tlo, thi;                                                     \
            asm("{\n\t.reg .b64 t;\n\t"                                         \
                "fma.rn.f32x2 t, %2, %3, %4;\n\t"                               \
                "fma.rn.f32x2 t, %5, %6, t;\n\t"                                \
                "fma.rn.f32x2 t, %7, %8, t;\n\t"                                \
                "mov.b64 {%0, %1}, t;\n\t}"                                     \
                : "=f"(tlo), "=f"(thi)                                          \
                : "l"(qx2[0]), "l"(A.x), "l"(Bv.y),                             \
                  "l"(qy2[0]), "l"(A.y), "l"(qz2[0]), "l"(Bv.x));               \
            mE0 = fminf(mE0, tlo); mO0 = fminf(mO0, thi);                       \
            asm("{\n\t.reg .b64 t;\n\t"                                         \
                "fma.rn.f32x2 t, %2, %3, %4;\n\t"                               \
                "fma.rn.f32x2 t, %5, %6, t;\n\t"                                \
                "fma.rn.f32x2 t, %7, %8, t;\n\t"                                \
                "mov.b64 {%0, %1}, t;\n\t}"                                     \
                : "=f"(tlo), "=f"(thi)                                          \
                : "l"(qx2[1]), "l"(A.x), "l"(Bv.y),                             \
                  "l"(qy2[1]), "l"(A.y), "l"(qz2[1]), "l"(Bv.x));               \
            mE1 = fminf(mE1, tlo); mO1 = fminf(mO1, thi);                       \
        }                                                                       \
        float m0 = fminf(mE0, mO0);                                             \
        if (m0 < best[0]) { best[0] = m0; gidw[0] = (G); bestd[0] = m0 + cc[0]; } \
        float m1 = fminf(mE1, mO1);                                             \
        if (m1 < best[1]) { best[1] = m1; gidw[1] = (G); bestd[1] = m1 + cc[1]; } \
    }

// db = dir*B + b.  dir 0: queries = gts, refs = preds. dir 1: swapped.
__global__ __launch_bounds__(TPB, 1) void nn_kernel() {
    extern __shared__ float sm[];
    float* s_tile = sm;                         // 32768 floats, jj-interleaved
    int*   s_sidx = (int*)(sm + 32768);         // 8192 orig indices
    float* s_glo  = sm + 32768 + 8192;          // 256 sampled group lo x
    float* s_ghi  = s_glo + NGROUPS;            // 256 sampled group hi x

    const int tid = threadIdx.x;
    const int db  = blockIdx.y;
    const int b   = db & 3;
    const int dir = db >> 2;
    const int qc  = (dir == 0) ? b : 4 + b;
    const int rc  = (dir == 0) ? 4 + b : b;
    const float4* gr  = g_sorted + rc * N_CONST;
    const int*    gri = g_sidx   + rc * N_CONST;
    const float4* gq  = g_sorted + qc * N_CONST;
    const int*    gqi = g_sidx   + qc * N_CONST;

    for (int j = tid; j < N_CONST; j += TPB) {
        float4 p = gr[j];
        int jj = j >> 1, h = j & 1;
        float* pp = s_tile + jj * 8;
        pp[0 + h] = p.x; pp[2 + h] = p.y; pp[4 + h] = p.z; pp[6 + h] = p.w;
        s_sidx[j] = gri[j];
    }
    __syncthreads();
    if (tid < NGROUPS) {
        int p0 = tid * GROUP, p1 = tid * GROUP + GROUP - 1;
        s_glo[tid] = s_tile[(p0 >> 1) * 8 + (p0 & 1)];
        s_ghi[tid] = s_tile[(p1 >> 1) * 8 + (p1 & 1)];
    }
    __syncthreads();

    float qx[QPT], cc[QPT], qxs[QPT], qys[QPT], qzs[QPT];
    unsigned long long qx2[QPT], qy2[QPT], qz2[QPT];
    float best[QPT], bestd[QPT];
    int gidw[QPT], oq[QPT], ghome[QPT];

    #pragma unroll
    for (int k = 0; k < QPT; k++) {
        int qpos = blockIdx.x * QPC + tid * QPT + k;   // warp: 64 sorted-adjacent
        float4 qp = gq[qpos];
        oq[k] = gqi[qpos];
        qx[k] = qp.x; cc[k] = qp.w;
        qxs[k] = -2.0f * qp.x; qys[k] = -2.0f * qp.y; qzs[k] = -2.0f * qp.z;
        asm("mov.b64 %0, {%1, %1};" : "=l"(qx2[k]) : "f"(qxs[k]));
        asm("mov.b64 %0, {%1, %1};" : "=l"(qy2[k]) : "f"(qys[k]));
        asm("mov.b64 %0, {%1, %1};" : "=l"(qz2[k]) : "f"(qzs[k]));
        best[k] = CUDART_INF_F; bestd[k] = CUDART_INF_F; gidw[k] = 0;
        int lo = 0, hi = NGROUPS - 1;
        #pragma unroll
        for (int it = 0; it < 8; it++) {
            int mid = (lo + hi + 1) >> 1;
            if (s_glo[mid] <= qx[k]) lo = mid; else hi = mid - 1;
        }
        ghome[k] = lo;
    }

    int gmn = min(ghome[0], ghome[1]);
    int gmx = max(ghome[0], ghome[1]);
    #pragma unroll
    for (int o = 16; o; o >>= 1) {
        gmn = min(gmn, __shfl_xor_sync(0xffffffffu, gmn, o));
        gmx = max(gmx, __shfl_xor_sync(0xffffffffu, gmx, o));
    }
    for (int g = gmn; g <= gmx; g++) NN_BODY(g);

    for (int g = gmx + 1; g < NGROUPS; g++) {
        float e0 = s_glo[g] - qx[0];
        float e1 = s_glo[g] - qx[1];
        bool need = (e0 * e0 <= bestd[0] * 1.000002f + 1e-7f)
                 || (e1 * e1 <= bestd[1] * 1.000002f + 1e-7f);
        if (!__any_sync(0xffffffffu, need)) break;
        NN_BODY(g);
    }
    for (int g = gmn - 1; g >= 0; g--) {
        float e0 = qx[0] - s_ghi[g];
        float e1 = qx[1] - s_ghi[g];
        bool need = (e0 * e0 <= bestd[0] * 1.000002f + 1e-7f)
                 || (e1 * e1 <= bestd[1] * 1.000002f + 1e-7f);
        if (!__any_sync(0xffffffffu, need)) break;
        NN_BODY(g);
    }

    #pragma unroll
    for (int k = 0; k < QPT; k++) {
        const int base = gidw[k] * GROUP;
        int bi = 0x7fffffff;
        #pragma unroll 8
        for (int j = 0; j < GROUP; j++) {
            int pos = base + j;
            const float* p = s_tile + (pos >> 1) * 8;
            int h = pos & 1;
            float t = fmaf(qxs[k], p[0 + h], p[6 + h]);
            t = fmaf(qys[k], p[2 + h], t);
            t = fmaf(qzs[k], p[4 + h], t);
            if (t == best[k]) bi = min(bi, s_sidx[pos]);
        }
        g_idx[db * N_CONST + oq[k]] = bi;
        atomicAdd(&g_cnt[db * N_CONST + bi], 1);
    }
}

// ---- wide finalize (R11-winning config) ----
__global__ __launch_bounds__(FIN_TPB) void finalize_partial(const float* __restrict__ gts,
                                                            const float* __restrict__ preds) {
    __shared__ float ssum[FIN_TPB];
    const int e = blockIdx.x * FIN_TPB + threadIdx.x;
    const int db = e / N_CONST;
    const int q  = e - db * N_CONST;
    const int b  = db & (B_CONST - 1);
    const int dir = db >> 2;
    const float* qptr = (dir == 0) ? gts : preds;
    const float* rptr = (dir == 0) ? preds : gts;
    const float* qb = qptr + (long)b * N_CONST * 3;
    const float* rb = rptr + (long)b * N_CONST * 3;

    int id = g_idx[e];
    float dx = qb[3 * q + 0] - rb[3 * id + 0];
    float dy = qb[3 * q + 1] - rb[3 * id + 1];
    float dz = qb[3 * q + 2] - rb[3 * id + 2];
    float d  = dx * dx + dy * dy + dz * dz;
    float c  = (float)g_cnt[db * N_CONST + id];
    float acc = 1.0f - expf(-d) / (c + 1e-6f);   // ALPHA=1, N_LAMBDA=1, frac=1

    ssum[threadIdx.x] = acc;
    __syncthreads();
    for (int off = FIN_TPB / 2; off > 0; off >>= 1) {
        if (threadIdx.x < off) ssum[threadIdx.x] += ssum[threadIdx.x + off];
        __syncthreads();
    }
    if (threadIdx.x == 0) g_part[blockIdx.x] = ssum[0];
}

__global__ void finalize_final(float* __restrict__ out) {
    int b = threadIdx.x;
    if (b >= B_CONST) return;
    float s = 0.0f;
    #pragma unroll
    for (int dir = 0; dir < 2; dir++) {
        int db = dir * B_CONST + b;
        #pragma unroll
        for (int c = 0; c < FIN_CPD; c++)
            s += g_part[db * FIN_CPD + c];
    }
    out[b] = s / (2.0f * (float)N_CONST);
}

extern "C" void kernel_launch(void* const* d_in, const int* in_sizes, int n_in,
                              void* d_out, int out_size) {
    const float* gts   = (const float*)d_in[0];
    const float* preds = (const float*)d_in[1];
    float* out = (float*)d_out;

    cudaFuncSetAttribute(sortB, cudaFuncAttributeMaxDynamicSharedMemorySize, SORTB_SMEM);
    cudaFuncSetAttribute(nn_kernel, cudaFuncAttributeMaxDynamicSharedMemorySize, NN_SMEM);

    sortA<<<dim3(SEGS, NCLOUD), 256>>>(gts, preds);
    sortB<<<NCLOUD, 1024, SORTB_SMEM>>>();
    sortC<<<dim3(SEGS, NCLOUD), 256>>>();
    nn_kernel<<<dim3(QCHUNKS, 2 * B_CONST), TPB, NN_SMEM>>>();
    finalize_partial<<<FIN_BLOCKS, FIN_TPB>>>(gts, preds);
    finalize_final<<<1, 32>>>(out);
}